// round 4
// baseline (speedup 1.0000x reference)
#include <cuda_runtime.h>

// Problem constants
#define BB 8
#define CC 32
#define DD 32
#define TT 32
#define HH 96
#define WW 96
#define MT 8
#define MS 16
#define BC (BB*CC)        // 256
#define BD (BB*DD)        // 256
#define HW (HH*WW)        // 9216
#define NMODE (MT*MS*MS)  // 2048
#define TWO_PI 6.28318530717958647692f

// ---------------- scratch (static device globals; no allocation) ----------------
__device__ float g_F1r[BC*MT*HW];        // after T-DFT: (bc, kt, h, w)
__device__ float g_F1i[BC*MT*HW];
__device__ float g_F2r[BC*MT*MS*WW];     // after H-DFT: (bc, kt, kx, w)
__device__ float g_F2i[BC*MT*MS*WW];
__device__ float g_F3r[BC*NMODE];        // after W-DFT: (bc, kt, kx, ky)
__device__ float g_F3i[BC*NMODE];
__device__ float g_Sr [BD*NMODE];        // after mix:   (bd, kt, kx, ky)
__device__ float g_Si [BD*NMODE];
__device__ float g_A1r[BD*MT*MS*WW];     // after W-exp: (bd, kt, kx, w)
__device__ float g_A1i[BD*MT*MS*WW];
__device__ float g_A2r[BD*MT*HW];        // after H-exp: (bd, kt, h, w)
__device__ float g_A2i[BD*MT*HW];
__device__ float g_Wtr[NMODE*CC*DD];     // weights transposed: (m, c, d), scale folded
__device__ float g_Wti[NMODE*CC*DD];

// ---------------- K0: transpose + fold weights ----------------
// Wt[m][c][d] = w[c][d][m] * cky(ky) / (T*H*W)   (ortho fwd * ortho inv = 1/N)
__global__ void k0_weights(const float* __restrict__ wr, const float* __restrict__ wi) {
    int o = blockIdx.x * blockDim.x + threadIdx.x;   // 0 .. NMODE*CC*DD-1 (exact)
    int d = o & 31;
    int c = (o >> 5) & 31;
    int m = o >> 10;
    int ky = m & 15;
    float scale = (ky == 0 ? 1.0f : 2.0f) * (1.0f / 294912.0f);
    size_t iidx = ((size_t)(c * DD + d)) * NMODE + m;
    g_Wtr[o] = wr[iidx] * scale;
    g_Wti[o] = wi[iidx] * scale;
}

// ---------------- K1: T-DFT (real -> complex), kt = 0..7 ----------------
// X1[kt] = sum_t x[t] * exp(-2pi*i*kt*t/32)
// thread: one (bc, h, 4 consecutive w), all 8 kt. 64 accumulators.
__global__ void k1_tdft(const float* __restrict__ x) {
    __shared__ float2 cs[TT*MT];   // [t][kt] = (cos, sin)
    int tid = threadIdx.x;
    for (int i = tid; i < TT*MT; i += blockDim.x) {
        int t = i >> 3, k = i & 7;
        int p = (t * k) & (TT - 1);
        float s, c; sincosf(TWO_PI * (float)p / (float)TT, &s, &c);
        cs[i] = make_float2(c, s);
    }
    __syncthreads();

    int g  = blockIdx.x * blockDim.x + tid;          // 0 .. BC*HH*24-1 (exact)
    int w4 = g % 24;
    int h  = (g / 24) % HH;
    int bc = g / (24 * HH);
    const float* xp = x + (size_t)bc * TT * HW + h * WW + w4 * 4;

    float ar[MT][4], ai[MT][4];
#pragma unroll
    for (int k = 0; k < MT; k++)
#pragma unroll
        for (int j = 0; j < 4; j++) { ar[k][j] = 0.0f; ai[k][j] = 0.0f; }

#pragma unroll 4
    for (int t = 0; t < TT; t++) {
        float4 v = *reinterpret_cast<const float4*>(xp + (size_t)t * HW);
        float vv[4] = {v.x, v.y, v.z, v.w};
#pragma unroll
        for (int k = 0; k < MT; k++) {
            float2 e = cs[t * MT + k];
#pragma unroll
            for (int j = 0; j < 4; j++) {
                ar[k][j] = fmaf(vv[j],  e.x, ar[k][j]);
                ai[k][j] = fmaf(-vv[j], e.y, ai[k][j]);
            }
        }
    }
#pragma unroll
    for (int k = 0; k < MT; k++) {
        size_t o = ((size_t)(bc * MT + k)) * HW + h * WW + w4 * 4;
        *reinterpret_cast<float4*>(g_F1r + o) = make_float4(ar[k][0], ar[k][1], ar[k][2], ar[k][3]);
        *reinterpret_cast<float4*>(g_F1i + o) = make_float4(ai[k][0], ai[k][1], ai[k][2], ai[k][3]);
    }
}

// ---------------- K2: H-DFT (complex), kx = 0..15 ----------------
// X2[kx] = sum_h X1[h] * exp(-2pi*i*kx*h/96)
// thread: one (slab = bc*8+kt, 2 consecutive w), all 16 kx. 64 accumulators.
__global__ void k2_hdft() {
    __shared__ float2 cs[HH*MS];   // [h][kx]
    int tid = threadIdx.x;
    for (int i = tid; i < HH*MS; i += blockDim.x) {
        int h = i >> 4, k = i & 15;
        int p = (h * k) % HH;
        float s, c; sincosf(TWO_PI * (float)p / (float)HH, &s, &c);
        cs[i] = make_float2(c, s);
    }
    __syncthreads();

    int g    = blockIdx.x * blockDim.x + tid;        // 0 .. 2048*48-1 (exact)
    int wg   = g % 48;
    int slab = g / 48;
    int w0   = wg * 2;
    const float* br = g_F1r + (size_t)slab * HW + w0;
    const float* bi = g_F1i + (size_t)slab * HW + w0;

    float ar[MS][2], ai[MS][2];
#pragma unroll
    for (int k = 0; k < MS; k++) { ar[k][0]=ar[k][1]=ai[k][0]=ai[k][1]=0.0f; }

    for (int h = 0; h < HH; h++) {
        float2 xr = *reinterpret_cast<const float2*>(br + h * WW);
        float2 xi = *reinterpret_cast<const float2*>(bi + h * WW);
#pragma unroll
        for (int k = 0; k < MS; k++) {
            float2 e = cs[h * MS + k];
            // (xr + i*xi) * (c - i*s): re = xr*c + xi*s ; im = xi*c - xr*s
            ar[k][0] = fmaf(xr.x, e.x, fmaf(xi.x,  e.y, ar[k][0]));
            ai[k][0] = fmaf(xi.x, e.x, fmaf(-xr.x, e.y, ai[k][0]));
            ar[k][1] = fmaf(xr.y, e.x, fmaf(xi.y,  e.y, ar[k][1]));
            ai[k][1] = fmaf(xi.y, e.x, fmaf(-xr.y, e.y, ai[k][1]));
        }
    }
#pragma unroll
    for (int k = 0; k < MS; k++) {
        size_t o = ((size_t)(slab * MS + k)) * WW + w0;
        *reinterpret_cast<float2*>(g_F2r + o) = make_float2(ar[k][0], ar[k][1]);
        *reinterpret_cast<float2*>(g_F2i + o) = make_float2(ai[k][0], ai[k][1]);
    }
}

// ---------------- K3: W-DFT (complex), ky = 0..15 ----------------
// thread: one (row = slab*16+kx, ky). Row data (96 complex) is hot in L1.
__global__ void k3_wdft() {
    __shared__ float2 cs[WW*MS];   // [w][ky]
    int tid = threadIdx.x;
    for (int i = tid; i < WW*MS; i += blockDim.x) {
        int w = i >> 4, k = i & 15;
        int p = (w * k) % WW;
        float s, c; sincosf(TWO_PI * (float)p / (float)WW, &s, &c);
        cs[i] = make_float2(c, s);
    }
    __syncthreads();

    int g  = blockIdx.x * blockDim.x + tid;          // 0 .. 32768*16-1 (exact)
    int ky = g & 15;
    int r  = g >> 4;
    const float* br = g_F2r + (size_t)r * WW;
    const float* bi = g_F2i + (size_t)r * WW;
    float sr = 0.0f, si = 0.0f;
#pragma unroll 4
    for (int w = 0; w < WW; w++) {
        float xr = __ldg(br + w), xi = __ldg(bi + w);
        float2 e = cs[w * MS + ky];
        sr = fmaf(xr, e.x, fmaf(xi,  e.y, sr));
        si = fmaf(xi, e.x, fmaf(-xr, e.y, si));
    }
    g_F3r[(size_t)r * MS + ky] = sr;
    g_F3i[(size_t)r * MS + ky] = si;
}

// ---------------- K4: channel mix (complex GEMM per mode) ----------------
// S[b,d,m] = sum_c X[b,c,m] * Wt[m,c,d]   (scale already folded into Wt)
__global__ void k4_mix() {
    int m = blockIdx.x;
    __shared__ float Xr[BB*CC], Xi[BB*CC];
    int tid = threadIdx.x;                            // 256 = 8 b * 32 d
    for (int i = tid; i < BB*CC; i += blockDim.x) {
        Xr[i] = g_F3r[(size_t)i * NMODE + m];
        Xi[i] = g_F3i[(size_t)i * NMODE + m];
    }
    __syncthreads();
    int b = tid >> 5, d = tid & 31;
    const float* wr = g_Wtr + (size_t)m * CC * DD + d;
    const float* wi = g_Wti + (size_t)m * CC * DD + d;
    float sr = 0.0f, si = 0.0f;
#pragma unroll 8
    for (int c = 0; c < CC; c++) {
        float xr = Xr[b * CC + c], xi = Xi[b * CC + c];
        float a  = wr[c * DD],     bb = wi[c * DD];
        sr = fmaf(xr, a,  fmaf(-xi, bb, sr));
        si = fmaf(xr, bb, fmaf( xi, a,  si));
    }
    g_Sr[(size_t)(b * DD + d) * NMODE + m] = sr;
    g_Si[(size_t)(b * DD + d) * NMODE + m] = si;
}

// ---------------- K5: W-expand (16 -> 96), e^{+i theta} ----------------
// thread: one (row = bd*128+kt*16+kx, 4 consecutive w).
__global__ void k5_wexp() {
    __shared__ float2 cs[MS*WW];   // [ky][w]
    int tid = threadIdx.x;
    for (int i = tid; i < MS*WW; i += blockDim.x) {
        int ky = i / WW, w = i % WW;
        int p = (ky * w) % WW;
        float s, c; sincosf(TWO_PI * (float)p / (float)WW, &s, &c);
        cs[i] = make_float2(c, s);
    }
    __syncthreads();

    int g  = blockIdx.x * blockDim.x + tid;          // 0 .. 32768*24-1 (exact)
    int wg = g % 24;
    int r  = g / 24;
    int w0 = wg * 4;
    const float* pr = g_Sr + (size_t)r * MS;
    const float* pi = g_Si + (size_t)r * MS;

    float ar[4] = {0,0,0,0}, ai[4] = {0,0,0,0};
#pragma unroll
    for (int ky = 0; ky < MS; ky++) {
        float sr = pr[ky], si = pi[ky];
#pragma unroll
        for (int j = 0; j < 4; j++) {
            float2 e = cs[ky * WW + w0 + j];
            // (sr + i*si) * (c + i*s): re = sr*c - si*s ; im = sr*s + si*c
            ar[j] = fmaf(sr, e.x, fmaf(-si, e.y, ar[j]));
            ai[j] = fmaf(sr, e.y, fmaf( si, e.x, ai[j]));
        }
    }
    size_t o = (size_t)r * WW + w0;
    *reinterpret_cast<float4*>(g_A1r + o) = make_float4(ar[0], ar[1], ar[2], ar[3]);
    *reinterpret_cast<float4*>(g_A1i + o) = make_float4(ai[0], ai[1], ai[2], ai[3]);
}

// ---------------- K6: H-expand (16 -> 96), e^{+i theta} ----------------
// thread: one (slab = bd*8+kt, 2 w, 16 h of one of 6 h-groups). 64 accumulators.
__global__ void k6_hexp() {
    __shared__ float2 cs[MS*HH];   // [kx][h]
    int tid = threadIdx.x;
    for (int i = tid; i < MS*HH; i += blockDim.x) {
        int kx = i / HH, h = i % HH;
        int p = (kx * h) % HH;
        float s, c; sincosf(TWO_PI * (float)p / (float)HH, &s, &c);
        cs[i] = make_float2(c, s);
    }
    __syncthreads();

    int g    = blockIdx.x * blockDim.x + tid;        // 0 .. 2048*6*48-1 (exact)
    int wg   = g % 48;
    int hg   = (g / 48) % 6;
    int slab = g / (48 * 6);
    int w0   = wg * 2;
    int h0   = hg * 16;

    float ar[16][2], ai[16][2];
#pragma unroll
    for (int j = 0; j < 16; j++) { ar[j][0]=ar[j][1]=ai[j][0]=ai[j][1]=0.0f; }

#pragma unroll
    for (int kx = 0; kx < MS; kx++) {
        size_t ib = ((size_t)(slab * MS + kx)) * WW + w0;
        float2 xr = *reinterpret_cast<const float2*>(g_A1r + ib);
        float2 xi = *reinterpret_cast<const float2*>(g_A1i + ib);
#pragma unroll
        for (int j = 0; j < 16; j++) {
            float2 e = cs[kx * HH + h0 + j];
            ar[j][0] = fmaf(xr.x, e.x, fmaf(-xi.x, e.y, ar[j][0]));
            ai[j][0] = fmaf(xr.x, e.y, fmaf( xi.x, e.x, ai[j][0]));
            ar[j][1] = fmaf(xr.y, e.x, fmaf(-xi.y, e.y, ar[j][1]));
            ai[j][1] = fmaf(xr.y, e.y, fmaf( xi.y, e.x, ai[j][1]));
        }
    }
#pragma unroll
    for (int j = 0; j < 16; j++) {
        size_t o = ((size_t)slab * HH + h0 + j) * WW + w0;
        *reinterpret_cast<float2*>(g_A2r + o) = make_float2(ar[j][0], ar[j][1]);
        *reinterpret_cast<float2*>(g_A2i + o) = make_float2(ai[j][0], ai[j][1]);
    }
}

// ---------------- K7: T-expand (8 -> 32) + real part -> output ----------------
// out[t] = sum_kt ( A2r*cos - A2i*sin ), theta = 2pi*kt*t/32
// thread: one (bd, h, 2 w, 16 t of one t-half). 32 accumulators.
__global__ void k7_texp(float* __restrict__ out) {
    __shared__ float2 cs[MT*TT];   // [kt][t]
    int tid = threadIdx.x;
    for (int i = tid; i < MT*TT; i += blockDim.x) {
        int kt = i >> 5, t = i & 31;
        int p = (kt * t) & (TT - 1);
        float s, c; sincosf(TWO_PI * (float)p / (float)TT, &s, &c);
        cs[i] = make_float2(c, s);
    }
    __syncthreads();

    int g    = blockIdx.x * blockDim.x + tid;        // 0 .. 256*96*2*48-1 (exact)
    int wg   = g % 48;
    int th   = (g / 48) & 1;
    int rest = g / 96;
    int h    = rest % HH;
    int bd   = rest / HH;
    int w0   = wg * 2;
    int t0   = th * 16;

    float o[16][2];
#pragma unroll
    for (int j = 0; j < 16; j++) { o[j][0] = 0.0f; o[j][1] = 0.0f; }

#pragma unroll
    for (int kt = 0; kt < MT; kt++) {
        size_t ib = (((size_t)bd * MT + kt) * HH + h) * WW + w0;
        float2 xr = *reinterpret_cast<const float2*>(g_A2r + ib);
        float2 xi = *reinterpret_cast<const float2*>(g_A2i + ib);
#pragma unroll
        for (int j = 0; j < 16; j++) {
            float2 e = cs[kt * TT + t0 + j];
            o[j][0] = fmaf(xr.x, e.x, fmaf(-xi.x, e.y, o[j][0]));
            o[j][1] = fmaf(xr.y, e.x, fmaf(-xi.y, e.y, o[j][1]));
        }
    }
#pragma unroll
    for (int j = 0; j < 16; j++) {
        int t = t0 + j;
        size_t oo = ((size_t)bd * TT + t) * HW + h * WW + w0;
        *reinterpret_cast<float2*>(out + oo) = make_float2(o[j][0], o[j][1]);
    }
}

// ---------------- launch ----------------
extern "C" void kernel_launch(void* const* d_in, const int* in_sizes, int n_in,
                              void* d_out, int out_size) {
    (void)in_sizes; (void)n_in; (void)out_size;
    const float* x  = (const float*)d_in[0];
    const float* wr = (const float*)d_in[1];
    const float* wi = (const float*)d_in[2];
    float* out = (float*)d_out;

    k0_weights<<<8192, 256>>>(wr, wi);   // NMODE*CC*DD / 256
    k1_tdft  <<<2304, 256>>>(x);         // BC*HH*24 / 256
    k2_hdft  <<<384,  256>>>();          // 2048*48 / 256
    k3_wdft  <<<2048, 256>>>();          // 32768*16 / 256
    k4_mix   <<<2048, 256>>>();          // one block per mode
    k5_wexp  <<<3072, 256>>>();          // 32768*24 / 256
    k6_hexp  <<<2304, 256>>>();          // 2048*6*48 / 256
    k7_texp  <<<9216, 256>>>(out);       // 256*96*2*48 / 256
}

// round 5
// speedup vs baseline: 1.2115x; 1.2115x over previous
#include <cuda_runtime.h>

// Problem constants
#define BB 8
#define CC 32
#define DD 32
#define TT 32
#define HH 96
#define WW 96
#define MT 8
#define MS 16
#define BC (BB*CC)        // 256
#define BD (BB*DD)        // 256
#define HW (HH*WW)        // 9216
#define NMODE (MT*MS*MS)  // 2048
#define TWO_PI 6.28318530717958647692f

// ---------------- scratch (static device globals; no allocation) ----------------
__device__ float g_F2r[BC*MT*MS*WW];     // after T+H DFT: (bc, kt, kx, w)
__device__ float g_F2i[BC*MT*MS*WW];
__device__ float g_F3r[BC*NMODE];        // after W-DFT: (bc, kt, kx, ky)
__device__ float g_F3i[BC*NMODE];
__device__ float g_Sr [BD*NMODE];        // after mix:   (bd, kt, kx, ky)
__device__ float g_Si [BD*NMODE];
__device__ float g_Wtr[NMODE*CC*DD];     // weights transposed: (m, c*32+d), scale folded
__device__ float g_Wti[NMODE*CC*DD];

// ---------------- compile-time trig (Taylor, double precision) ----------------
__host__ __device__ constexpr double ct_cos(double x) {
    double x2 = x * x, t = 1.0, s = 1.0;
    for (int k = 1; k <= 26; k++) { t *= -x2 / ((2.0*k - 1.0) * (2.0*k)); s += t; }
    return s;
}
__host__ __device__ constexpr double ct_sin(double x) {
    double x2 = x * x, t = x, s = x;
    for (int k = 1; k <= 26; k++) { t *= -x2 / ((2.0*k) * (2.0*k + 1.0)); s += t; }
    return s;
}
// cos/sin(2*pi*P/N) as a compile-time float literal -> FFMA immediate operand
template<int P, int N> __device__ __forceinline__ float KC() {
    constexpr int q0 = ((P % N) + N) % N;
    constexpr int q  = (q0 > N/2) ? q0 - N : q0;
    constexpr float v = (float)ct_cos(6.283185307179586476925286766559 * (double)q / (double)N);
    return v;
}
template<int P, int N> __device__ __forceinline__ float KS() {
    constexpr int q0 = ((P % N) + N) % N;
    constexpr int q  = (q0 > N/2) ? q0 - N : q0;
    constexpr float v = (float)ct_sin(6.283185307179586476925286766559 * (double)q / (double)N);
    return v;
}

// ---------------- compile-time unroller (indices become constexpr) ----------------
template<int I> struct Ic { static constexpr int v = I; };
template<int I, int E, class F> __device__ __forceinline__ void UNR(F&& f) {
    if constexpr (I < E) { f(Ic<I>{}); UNR<I+1, E>(f); }
}

// ---------------- K0: tiled transpose + fold weights ----------------
// Wt[m][c*32+d] = w[c][d][m] * cky(ky) / (T*H*W)
__global__ void __launch_bounds__(256) k0_weights(const float* __restrict__ wr,
                                                  const float* __restrict__ wi) {
    __shared__ float tr[32][33], ti[32][33];
    int mt = (blockIdx.x & 63) << 5;   // 64 m-tiles  (NMODE/32)
    int ct = (blockIdx.x >> 6) << 5;   // 32 cd-tiles (1024/32)
    int lx = threadIdx.x & 31, ly = threadIdx.x >> 5;
#pragma unroll
    for (int yy = ly; yy < 32; yy += 8) {
        size_t ii = (size_t)(ct + yy) * NMODE + mt + lx;   // coalesced along m
        tr[yy][lx] = wr[ii];
        ti[yy][lx] = wi[ii];
    }
    __syncthreads();
#pragma unroll
    for (int yy = ly; yy < 32; yy += 8) {
        int m  = mt + yy;
        int cd = ct + lx;
        float sc = (((m & (MS-1)) == 0) ? 1.0f : 2.0f) * (1.0f / 294912.0f);
        size_t oo = (size_t)m * (CC*DD) + cd;              // coalesced along cd
        g_Wtr[oo] = tr[lx][yy] * sc;
        g_Wti[oo] = ti[lx][yy] * sc;
    }
}

// ---------------- KA: fused T-DFT + H-DFT  (x -> F2) ----------------
// block = (bc, 16-wide w window). phase1: Y[kt][h][wl] = T-DFT of x (smem).
// phase2: F2[kt][kx][w] = H-DFT of Y. All twiddles are FFMA immediates.
__global__ void __launch_bounds__(128) kA_fwd(const float* __restrict__ x) {
    extern __shared__ float sm[];
    float* Yr = sm;                     // [8][96][16]
    float* Yi = sm + MT*HH*16;
    const int tid = threadIdx.x;
    const int bc = blockIdx.x / 6;
    const int w0 = (blockIdx.x % 6) * 16;
    const float* xb = x + (size_t)bc * TT * HW + w0;

    const int wl = tid & 15;
    const int hs = tid >> 4;

    // phase1: T-DFT (real -> complex), e^{-i 2pi kt t / 32}
    for (int p = 0; p < 12; p++) {
        const int h = p * 8 + hs;
        const float* xp = xb + h * WW + wl;
        float ar[MT], ai[MT];
        UNR<0,MT>([&](auto K){ ar[decltype(K)::v] = 0.f; ai[decltype(K)::v] = 0.f; });
        UNR<0,TT>([&](auto T){
            constexpr int t = decltype(T)::v;
            float v = xp[(size_t)t * HW];
            UNR<0,MT>([&](auto K){
                constexpr int k  = decltype(K)::v;
                constexpr int pp = (t * k) & (TT - 1);
                ar[k] = fmaf(v,  KC<pp,TT>(), ar[k]);
                ai[k] = fmaf(v, -KS<pp,TT>(), ai[k]);
            });
        });
        UNR<0,MT>([&](auto K){
            constexpr int k = decltype(K)::v;
            Yr[k*(HH*16) + h*16 + wl] = ar[k];
            Yi[k*(HH*16) + h*16 + wl] = ai[k];
        });
    }
    __syncthreads();

    // phase2: H-DFT (complex), e^{-i 2pi kx h / 96}
    const int kt = tid >> 4;
    float fr[MS], fi[MS];
    UNR<0,MS>([&](auto K){ fr[decltype(K)::v] = 0.f; fi[decltype(K)::v] = 0.f; });
    const float* yr = Yr + kt*(HH*16) + wl;
    const float* yi = Yi + kt*(HH*16) + wl;
    UNR<0,HH>([&](auto H){
        constexpr int h = decltype(H)::v;
        float a = yr[h*16], b = yi[h*16];
        UNR<0,MS>([&](auto K){
            constexpr int kx = decltype(K)::v;
            constexpr int pp = (h * kx) % HH;
            // (a + i b) * (c - i s): re = a*c + b*s ; im = b*c - a*s
            fr[kx] = fmaf(a, KC<pp,HH>(), fmaf(b,  KS<pp,HH>(), fr[kx]));
            fi[kx] = fmaf(b, KC<pp,HH>(), fmaf(a, -KS<pp,HH>(), fi[kx]));
        });
    });
    size_t base = ((size_t)(bc*MT + kt) * MS) * WW + w0 + wl;
    UNR<0,MS>([&](auto K){
        constexpr int kx = decltype(K)::v;
        g_F2r[base + kx*WW] = fr[kx];
        g_F2i[base + kx*WW] = fi[kx];
    });
}

// ---------------- K3: W-DFT (F2 -> F3), one row per thread, 16 ky acc ----------------
__global__ void __launch_bounds__(128) k3_wdft() {
    int row = blockIdx.x * 128 + threadIdx.x;     // 32768 rows, exact
    const float4* br = reinterpret_cast<const float4*>(g_F2r + (size_t)row * WW);
    const float4* bi = reinterpret_cast<const float4*>(g_F2i + (size_t)row * WW);
    float fr[MS], fi[MS];
    UNR<0,MS>([&](auto K){ fr[decltype(K)::v] = 0.f; fi[decltype(K)::v] = 0.f; });
    UNR<0,24>([&](auto Q){
        constexpr int qq = decltype(Q)::v;
        float4 xr = br[qq], xi = bi[qq];
        UNR<0,4>([&](auto J){
            constexpr int j = decltype(J)::v;
            constexpr int w = qq * 4 + j;
            float a = (j == 0) ? xr.x : (j == 1) ? xr.y : (j == 2) ? xr.z : xr.w;
            float b = (j == 0) ? xi.x : (j == 1) ? xi.y : (j == 2) ? xi.z : xi.w;
            UNR<0,MS>([&](auto K){
                constexpr int ky = decltype(K)::v;
                constexpr int pp = (w * ky) % WW;
                fr[ky] = fmaf(a, KC<pp,WW>(), fmaf(b,  KS<pp,WW>(), fr[ky]));
                fi[ky] = fmaf(b, KC<pp,WW>(), fmaf(a, -KS<pp,WW>(), fi[ky]));
            });
        });
    });
    size_t o = (size_t)row * MS;
    UNR<0,MS>([&](auto K){
        constexpr int ky = decltype(K)::v;
        g_F3r[o + ky] = fr[ky];
        g_F3i[o + ky] = fi[ky];
    });
}

// ---------------- K4: channel mix (complex GEMM per mode) ----------------
__global__ void __launch_bounds__(256) k4_mix() {
    int m = blockIdx.x;
    __shared__ float Xr[BC], Xi[BC];
    int tid = threadIdx.x;
    Xr[tid] = g_F3r[(size_t)tid * NMODE + m];
    Xi[tid] = g_F3i[(size_t)tid * NMODE + m];
    __syncthreads();
    int b = tid >> 5, d = tid & 31;
    const float* wr = g_Wtr + (size_t)m * CC * DD + d;
    const float* wi = g_Wti + (size_t)m * CC * DD + d;
    float sr = 0.0f, si = 0.0f;
#pragma unroll 8
    for (int c = 0; c < CC; c++) {
        float xr = Xr[b*CC + c], xi = Xi[b*CC + c];
        float a  = wr[c*DD],     bb = wi[c*DD];
        sr = fmaf(xr, a,  fmaf(-xi, bb, sr));
        si = fmaf(xr, bb, fmaf( xi, a,  si));
    }
    g_Sr[(size_t)(b*DD + d) * NMODE + m] = sr;
    g_Si[(size_t)(b*DD + d) * NMODE + m] = si;
}

// ---------------- KB: fused W-expand + H-expand + T-expand  (S -> out) ----------------
// block = (bd, 16-wide w window). phase0: a1[kx] (regs) from S tile (e^{+i ky w}).
// phase1: Z[kt][h][wl] from a1 (e^{+i kx h}, imm). phase2: out = Re(T-exp) (imm).
__global__ void __launch_bounds__(128) kB_inv(float* __restrict__ out) {
    extern __shared__ float sm[];
    float* Zr = sm;                              // [8][96][16] = 12288 floats
    float* Zi = sm + 12288;
    // phase0 staging aliases the Z region (consumed before Z is written)
    float*  Ssr = sm;                            // 2048 floats
    float*  Ssi = sm + 2048;                     // 2048 floats
    float2* tab = reinterpret_cast<float2*>(sm + 4096);   // [ky][wl] 256 float2

    const int tid = threadIdx.x;
    const int bd = blockIdx.x / 6;
    const int w0 = (blockIdx.x % 6) * 16;

    {   // load S tile (coalesced) + build per-block w table
        const float* sr = g_Sr + (size_t)bd * NMODE;
        const float* si = g_Si + (size_t)bd * NMODE;
        for (int i = tid; i < NMODE; i += 128) { Ssr[i] = sr[i]; Ssi[i] = si[i]; }
        for (int i = tid; i < 256; i += 128) {
            int ky = i >> 4, wl2 = i & 15;
            float ssin, ccos;
            sincosf(TWO_PI * (float)((ky * (w0 + wl2)) % WW) / (float)WW, &ssin, &ccos);
            tab[i] = make_float2(ccos, ssin);
        }
    }
    __syncthreads();

    const int wl = tid & 15;
    const int kt = tid >> 4;

    // phase0: W-expand into registers, e^{+i 2pi ky w / 96}
    float a1r[MS], a1i[MS];
    UNR<0,MS>([&](auto KX){
        constexpr int kx = decltype(KX)::v;
        const float* pr = Ssr + (kt*MS + kx) * MS;
        const float* pi = Ssi + (kt*MS + kx) * MS;
        float rr = 0.f, ii = 0.f;
        UNR<0,MS>([&](auto KY){
            constexpr int ky = decltype(KY)::v;
            float2 e = tab[ky*16 + wl];
            float sv = pr[ky], iv = pi[ky];
            rr = fmaf(sv, e.x, fmaf(-iv, e.y, rr));
            ii = fmaf(sv, e.y, fmaf( iv, e.x, ii));
        });
        a1r[kx] = rr; a1i[kx] = ii;
    });
    __syncthreads();   // all phase0 reads of Ssr/Ssi/tab done before Z overwrites them

    // phase1: H-expand, e^{+i 2pi kx h / 96} (immediates)
    UNR<0,HH>([&](auto H){
        constexpr int h = decltype(H)::v;
        float zr = 0.f, zi = 0.f;
        UNR<0,MS>([&](auto KX){
            constexpr int kx = decltype(KX)::v;
            constexpr int pp = (kx * h) % HH;
            zr = fmaf(a1r[kx], KC<pp,HH>(), fmaf(-a1i[kx], KS<pp,HH>(), zr));
            zi = fmaf(a1r[kx], KS<pp,HH>(), fmaf( a1i[kx], KC<pp,HH>(), zi));
        });
        Zr[kt*(HH*16) + h*16 + wl] = zr;
        Zi[kt*(HH*16) + h*16 + wl] = zi;
    });
    __syncthreads();

    // phase2: T-expand + real part -> out, e^{+i 2pi kt t / 32} (immediates)
    float* ob = out + (size_t)bd * TT * HW + w0;
    const int hs = tid >> 4;
    for (int p = 0; p < 12; p++) {
        const int h = p * 8 + hs;
        float zr[MT], zi[MT];
        UNR<0,MT>([&](auto K){
            constexpr int k = decltype(K)::v;
            zr[k] = Zr[k*(HH*16) + h*16 + wl];
            zi[k] = Zi[k*(HH*16) + h*16 + wl];
        });
        float* op = ob + h * WW + wl;
        UNR<0,TT>([&](auto T){
            constexpr int t = decltype(T)::v;
            float o = 0.f;
            UNR<0,MT>([&](auto K){
                constexpr int k  = decltype(K)::v;
                constexpr int pp = (k * t) & (TT - 1);
                o = fmaf(zr[k], KC<pp,TT>(), fmaf(-zi[k], KS<pp,TT>(), o));
            });
            op[(size_t)t * HW] = o;
        });
    }
}

// ---------------- launch ----------------
extern "C" void kernel_launch(void* const* d_in, const int* in_sizes, int n_in,
                              void* d_out, int out_size) {
    (void)in_sizes; (void)n_in; (void)out_size;
    const float* x  = (const float*)d_in[0];
    const float* wr = (const float*)d_in[1];
    const float* wi = (const float*)d_in[2];
    float* out = (float*)d_out;

    cudaFuncSetAttribute(kA_fwd, cudaFuncAttributeMaxDynamicSharedMemorySize, 98304);
    cudaFuncSetAttribute(kB_inv, cudaFuncAttributeMaxDynamicSharedMemorySize, 98304);

    k0_weights<<<2048, 256>>>(wr, wi);   // 64 m-tiles * 32 cd-tiles
    kA_fwd   <<<1536, 128, 98304>>>(x);  // 256 bc * 6 w-groups
    k3_wdft  <<<256,  128>>>();          // 32768 rows
    k4_mix   <<<2048, 256>>>();          // one block per mode
    kB_inv   <<<1536, 128, 98304>>>(out);// 256 bd * 6 w-groups
}

// round 6
// speedup vs baseline: 1.6490x; 1.3612x over previous
#include <cuda_runtime.h>

// Problem constants
#define BB 8
#define CC 32
#define DD 32
#define TT 32
#define HH 96
#define WW 96
#define MT 8
#define MS 16
#define BC (BB*CC)        // 256
#define BD (BB*DD)        // 256
#define HW (HH*WW)        // 9216
#define NMODE (MT*MS*MS)  // 2048
#define NROW (BC*MT*MS)   // 32768 rows of F2
#define TWO_PI 6.28318530717958647692f

// ---------------- scratch (static device globals; no allocation) ----------------
__device__ float g_F2r[WW*NROW];         // after T+H DFT, W-MAJOR: (w, bc*128+kt*16+kx)
__device__ float g_F2i[WW*NROW];
__device__ float g_F3r[BC*NMODE];        // after W-DFT: (bc, m)  m = kt*256+kx*16+ky
__device__ float g_F3i[BC*NMODE];
__device__ float g_Sr [BD*NMODE];        // after mix:   (bd, m)
__device__ float g_Si [BD*NMODE];
__device__ float g_Wtr[NMODE*CC*DD];     // weights transposed: (m, c*32+d), scale folded
__device__ float g_Wti[NMODE*CC*DD];

// ---------------- compile-time trig (Taylor, double precision) ----------------
__host__ __device__ constexpr double ct_cos(double x) {
    double x2 = x * x, t = 1.0, s = 1.0;
    for (int k = 1; k <= 26; k++) { t *= -x2 / ((2.0*k - 1.0) * (2.0*k)); s += t; }
    return s;
}
__host__ __device__ constexpr double ct_sin(double x) {
    double x2 = x * x, t = x, s = x;
    for (int k = 1; k <= 26; k++) { t *= -x2 / ((2.0*k) * (2.0*k + 1.0)); s += t; }
    return s;
}

// Twiddle cos/sin(2*pi*P/N) with exact 0 / +-1 at quadrant points
template<int P, int N> struct TW {
    static constexpr int    q0 = ((P % N) + N) % N;
    static constexpr int    aq = (q0 > N - q0) ? (N - q0) : q0;   // |angle| in [0, N/2]
    static constexpr int    ss = (q0 > N/2) ? -1 : 1;             // sin sign
    static constexpr bool c_zero = (4*aq == N);
    static constexpr bool s_zero = (aq == 0) || (2*aq == N);
    static constexpr float c =
        (aq == 0)     ? 1.0f  :
        (2*aq == N)   ? -1.0f :
        c_zero        ? 0.0f  :
        (float)ct_cos(6.283185307179586476925286766559 * (double)aq / (double)N);
    static constexpr float s =
        s_zero        ? 0.0f :
        (4*aq == N)   ? (ss > 0 ? 1.0f : -1.0f) :
        (float)(ss * ct_sin(6.283185307179586476925286766559 * (double)aq / (double)N));
};

// acc += SG * v * cos(2pi P/N)   (immediate-form FFMA; 0/+-1 elided)
template<int P, int N, int SG = 1>
__device__ __forceinline__ float fC(float v, float acc) {
    using T = TW<P, N>;
    constexpr float cc = (SG < 0) ? -T::c : T::c;
    if constexpr (T::c_zero)         return acc;
    else if constexpr (cc ==  1.0f)  return acc + v;
    else if constexpr (cc == -1.0f)  return acc - v;
    else                             return fmaf(v, cc, acc);
}
// acc += SG * v * sin(2pi P/N)
template<int P, int N, int SG = 1>
__device__ __forceinline__ float fS(float v, float acc) {
    using T = TW<P, N>;
    constexpr float sv = (SG < 0) ? -T::s : T::s;
    if constexpr (T::s_zero)         return acc;
    else if constexpr (sv ==  1.0f)  return acc + v;
    else if constexpr (sv == -1.0f)  return acc - v;
    else                             return fmaf(v, sv, acc);
}

// ---------------- compile-time unroller (indices become constexpr) ----------------
template<int I> struct Ic { static constexpr int v = I; };
template<int I, int E, class F> __device__ __forceinline__ void UNR(F&& f) {
    if constexpr (I < E) { f(Ic<I>{}); UNR<I+1, E>(f); }
}

// ---------------- K0: tiled transpose + fold weights ----------------
__global__ void __launch_bounds__(256) k0_weights(const float* __restrict__ wr,
                                                  const float* __restrict__ wi) {
    __shared__ float tr[32][33], ti[32][33];
    int mt = (blockIdx.x & 63) << 5;
    int ct = (blockIdx.x >> 6) << 5;
    int lx = threadIdx.x & 31, ly = threadIdx.x >> 5;
#pragma unroll
    for (int yy = ly; yy < 32; yy += 8) {
        size_t ii = (size_t)(ct + yy) * NMODE + mt + lx;
        tr[yy][lx] = wr[ii];
        ti[yy][lx] = wi[ii];
    }
    __syncthreads();
#pragma unroll
    for (int yy = ly; yy < 32; yy += 8) {
        int m  = mt + yy;
        int cd = ct + lx;
        float sc = (((m & (MS-1)) == 0) ? 1.0f : 2.0f) * (1.0f / 294912.0f);
        size_t oo = (size_t)m * (CC*DD) + cd;
        g_Wtr[oo] = tr[lx][yy] * sc;
        g_Wti[oo] = ti[lx][yy] * sc;
    }
}

// ---------------- KA: fused T-DFT + H-DFT  (x -> F2, w-major) ----------------
// smem Y layout: [h][kt][wl] -> h*128 + kt*16 + wl (conflict-light)
__global__ void __launch_bounds__(128) kA_fwd(const float* __restrict__ x) {
    extern __shared__ float sm[];
    float* Yr = sm;                     // 12288 floats
    float* Yi = sm + 12288;
    const int tid = threadIdx.x;
    const int bc = blockIdx.x / 6;
    const int w0 = (blockIdx.x % 6) * 16;
    const float* xb = x + (size_t)bc * TT * HW + w0;

    const int wl = tid & 15;
    const int hs = tid >> 4;

    // phase1: T-DFT (real -> complex), folded over t <-> 32-t
    for (int p = 0; p < 12; p++) {
        const int h = p * 8 + hs;
        const float* xp = xb + h * WW + wl;
        float ar[MT], ai[MT];
        float x0  = xp[0];
        float x16 = xp[16 * HW];
        UNR<0,MT>([&](auto K){ constexpr int k = decltype(K)::v;
            ar[k] = (k & 1) ? (x0 - x16) : (x0 + x16);
            ai[k] = 0.0f; });
        UNR<1,16>([&](auto T){ constexpr int t = decltype(T)::v;
            float a = xp[(size_t)t * HW];
            float b = xp[(size_t)(TT - t) * HW];
            float pt = a + b, mt = a - b;
            UNR<0,MT>([&](auto K){ constexpr int k = decltype(K)::v;
                ar[k] = fC<t*k, TT>(pt, ar[k]);
                ai[k] = fS<t*k, TT, -1>(mt, ai[k]);
            });
        });
        UNR<0,MT>([&](auto K){ constexpr int k = decltype(K)::v;
            Yr[h*128 + k*16 + wl] = ar[k];
            Yi[h*128 + k*16 + wl] = ai[k]; });
    }
    __syncthreads();

    // phase2: H-DFT (complex), folded over h <-> 96-h
    const int kt = tid >> 4;
    const float* yr = Yr + kt*16 + wl;
    const float* yi = Yi + kt*16 + wl;
    float fr[MS], fi[MS];
    {
        float a0  = yr[0],      b0  = yi[0];
        float a48 = yr[48*128], b48 = yi[48*128];
        UNR<0,MS>([&](auto K){ constexpr int kx = decltype(K)::v;
            fr[kx] = (kx & 1) ? (a0 - a48) : (a0 + a48);
            fi[kx] = (kx & 1) ? (b0 - b48) : (b0 + b48); });
    }
    UNR<1,48>([&](auto H){ constexpr int h = decltype(H)::v;
        float a  = yr[h*128],      b  = yi[h*128];
        float a2 = yr[(96-h)*128], b2 = yi[(96-h)*128];
        float pa = a + a2, ma = a - a2, pb = b + b2, mb = b - b2;
        UNR<0,MS>([&](auto K){ constexpr int kx = decltype(K)::v;
            // e^{-i th}: fr += pa*c + mb*s ; fi += pb*c - ma*s
            fr[kx] = fC<h*kx, HH>(pa, fS<h*kx, HH>(mb, fr[kx]));
            fi[kx] = fC<h*kx, HH>(pb, fS<h*kx, HH, -1>(ma, fi[kx]));
        });
    });
    // write F2 w-major: (w, bc*128 + kt*16 + kx)
    size_t base = (size_t)(w0 + wl) * NROW + bc*128 + kt*16;
    UNR<0,MS>([&](auto K){ constexpr int kx = decltype(K)::v;
        g_F2r[base + kx] = fr[kx];
        g_F2i[base + kx] = fi[kx]; });
}

// ---------------- K3: W-DFT (F2 -> F3), coalesced, folded over w <-> 96-w ----------------
__global__ void __launch_bounds__(128) k3_wdft() {
    int r = blockIdx.x * 128 + threadIdx.x;       // 32768 rows, exact
    const float* pr = g_F2r + r;
    const float* pi = g_F2i + r;
    float fr[MS], fi[MS];
    {
        float a0  = pr[0],                  b0  = pi[0];
        float a48 = pr[(size_t)48 * NROW],  b48 = pi[(size_t)48 * NROW];
        UNR<0,MS>([&](auto K){ constexpr int ky = decltype(K)::v;
            fr[ky] = (ky & 1) ? (a0 - a48) : (a0 + a48);
            fi[ky] = (ky & 1) ? (b0 - b48) : (b0 + b48); });
    }
    UNR<1,48>([&](auto WI){ constexpr int w = decltype(WI)::v;
        float a  = pr[(size_t)w * NROW],      b  = pi[(size_t)w * NROW];
        float a2 = pr[(size_t)(96-w) * NROW], b2 = pi[(size_t)(96-w) * NROW];
        float pa = a + a2, ma = a - a2, pb = b + b2, mb = b - b2;
        UNR<0,MS>([&](auto K){ constexpr int ky = decltype(K)::v;
            fr[ky] = fC<w*ky, WW>(pa, fS<w*ky, WW>(mb, fr[ky]));
            fi[ky] = fC<w*ky, WW>(pb, fS<w*ky, WW, -1>(ma, fi[ky]));
        });
    });
    size_t o = (size_t)r * MS;
    UNR<0,MS>([&](auto K){ constexpr int ky = decltype(K)::v;
        g_F3r[o + ky] = fr[ky];
        g_F3i[o + ky] = fi[ky]; });
}

// ---------------- K4: channel mix, 8 modes per block, coalesced X ----------------
#define K4M 8
__global__ void __launch_bounds__(256) k4_mix() {
    __shared__ float Xr[BC*K4M], Xi[BC*K4M];     // 16 KB
    const int m0 = blockIdx.x * K4M;
    const int tid = threadIdx.x;
    for (int i = tid; i < BC*K4M; i += 256) {
        int bcc = i / K4M, mm = i % K4M;
        Xr[i] = g_F3r[(size_t)bcc * NMODE + m0 + mm];
        Xi[i] = g_F3i[(size_t)bcc * NMODE + m0 + mm];
    }
    __syncthreads();
    const int b = tid >> 5, d = tid & 31;
    float sr[K4M], si[K4M];
#pragma unroll
    for (int j = 0; j < K4M; j++) { sr[j] = 0.0f; si[j] = 0.0f; }
#pragma unroll 4
    for (int c = 0; c < CC; c++) {
#pragma unroll
        for (int j = 0; j < K4M; j++) {
            float a  = g_Wtr[(size_t)(m0 + j) * (CC*DD) + c*DD + d];
            float bb = g_Wti[(size_t)(m0 + j) * (CC*DD) + c*DD + d];
            float xr = Xr[(b*CC + c)*K4M + j];
            float xi = Xi[(b*CC + c)*K4M + j];
            sr[j] = fmaf(xr, a,  fmaf(-xi, bb, sr[j]));
            si[j] = fmaf(xr, bb, fmaf( xi, a,  si[j]));
        }
    }
    size_t ob = (size_t)(b*DD + d) * NMODE + m0;
#pragma unroll
    for (int j = 0; j < K4M; j++) {
        g_Sr[ob + j] = sr[j];
        g_Si[ob + j] = si[j];
    }
}

// ---------------- KB: fused W-expand + H-expand + T-expand  (S -> out) ----------------
// smem Z layout: [h][kt][wl] -> h*128 + kt*16 + wl
__global__ void __launch_bounds__(128) kB_inv(float* __restrict__ out) {
    extern __shared__ float sm[];
    float* Zr = sm;                              // 12288 floats
    float* Zi = sm + 12288;
    float*  Ssr = sm;                            // phase0 staging aliases Z
    float*  Ssi = sm + 2048;
    float2* tab = reinterpret_cast<float2*>(sm + 4096);   // [ky][wl] 256 float2

    const int tid = threadIdx.x;
    const int bd = blockIdx.x / 6;
    const int w0 = (blockIdx.x % 6) * 16;

    {   // load S tile (coalesced) + per-block w table
        const float* sr = g_Sr + (size_t)bd * NMODE;
        const float* si = g_Si + (size_t)bd * NMODE;
        for (int i = tid; i < NMODE; i += 128) { Ssr[i] = sr[i]; Ssi[i] = si[i]; }
        for (int i = tid; i < 256; i += 128) {
            int ky = i >> 4, wl2 = i & 15;
            float ssin, ccos;
            sincosf(TWO_PI * (float)((ky * (w0 + wl2)) % WW) / (float)WW, &ssin, &ccos);
            tab[i] = make_float2(ccos, ssin);
        }
    }
    __syncthreads();

    const int wl = tid & 15;
    const int kt = tid >> 4;

    // phase0: W-expand into registers, e^{+i 2pi ky w / 96}
    float a1r[MS], a1i[MS];
    UNR<0,MS>([&](auto KX){ constexpr int kx = decltype(KX)::v;
        const float* pr = Ssr + (kt*MS + kx) * MS;
        const float* pi = Ssi + (kt*MS + kx) * MS;
        float rr = 0.f, ii = 0.f;
        UNR<0,MS>([&](auto KY){ constexpr int ky = decltype(KY)::v;
            float2 e = tab[ky*16 + wl];
            float sv = pr[ky], iv = pi[ky];
            rr = fmaf(sv, e.x, fmaf(-iv, e.y, rr));
            ii = fmaf(sv, e.y, fmaf( iv, e.x, ii));
        });
        a1r[kx] = rr; a1i[kx] = ii;
    });
    __syncthreads();   // phase0 reads done before Z overwrites

    // phase1: H-expand, folded over output h <-> 96-h
    // zr[h] = C - S, zr[96-h] = C + S ; zi[h] = C2 + S2, zi[96-h] = C2 - S2
    UNR<0,49>([&](auto H){ constexpr int h = decltype(H)::v;
        float C = 0.f, S = 0.f, C2 = 0.f, S2 = 0.f;
        UNR<0,MS>([&](auto KX){ constexpr int kx = decltype(KX)::v;
            C  = fC<kx*h, HH>(a1r[kx], C);
            C2 = fC<kx*h, HH>(a1i[kx], C2);
            S  = fS<kx*h, HH>(a1i[kx], S);
            S2 = fS<kx*h, HH>(a1r[kx], S2);
        });
        Zr[h*128 + kt*16 + wl] = C - S;
        Zi[h*128 + kt*16 + wl] = C2 + S2;
        if constexpr (h >= 1 && h <= 47) {
            Zr[(96-h)*128 + kt*16 + wl] = C + S;
            Zi[(96-h)*128 + kt*16 + wl] = C2 - S2;
        }
    });
    __syncthreads();

    // phase2: T-expand + real part, folded over output t <-> 32-t
    float* ob = out + (size_t)bd * TT * HW + w0;
    const int hs = tid >> 4;
    for (int p = 0; p < 12; p++) {
        const int h = p * 8 + hs;
        float zr[MT], zi[MT];
        UNR<0,MT>([&](auto K){ constexpr int k = decltype(K)::v;
            zr[k] = Zr[h*128 + k*16 + wl];
            zi[k] = Zi[h*128 + k*16 + wl]; });
        float* op = ob + h * WW + wl;
        {   // t = 0 and t = 16
            float s0 = 0.f, s16 = 0.f;
            UNR<0,MT>([&](auto K){ constexpr int k = decltype(K)::v;
                s0 += zr[k];
                s16 = (k & 1) ? (s16 - zr[k]) : (s16 + zr[k]); });
            op[0] = s0;
            op[(size_t)16 * HW] = s16;
        }
        UNR<1,16>([&](auto T){ constexpr int t = decltype(T)::v;
            float C = 0.f, S = 0.f;
            UNR<0,MT>([&](auto K){ constexpr int k = decltype(K)::v;
                C = fC<k*t, TT>(zr[k], C);
                S = fS<k*t, TT>(zi[k], S);
            });
            op[(size_t)t * HW]        = C - S;
            op[(size_t)(32 - t) * HW] = C + S;
        });
    }
}

// ---------------- launch ----------------
extern "C" void kernel_launch(void* const* d_in, const int* in_sizes, int n_in,
                              void* d_out, int out_size) {
    (void)in_sizes; (void)n_in; (void)out_size;
    const float* x  = (const float*)d_in[0];
    const float* wr = (const float*)d_in[1];
    const float* wi = (const float*)d_in[2];
    float* out = (float*)d_out;

    cudaFuncSetAttribute(kA_fwd, cudaFuncAttributeMaxDynamicSharedMemorySize, 98304);
    cudaFuncSetAttribute(kB_inv, cudaFuncAttributeMaxDynamicSharedMemorySize, 98304);

    k0_weights<<<2048, 256>>>(wr, wi);
    kA_fwd   <<<1536, 128, 98304>>>(x);   // 256 bc * 6 w-groups
    k3_wdft  <<<256,  128>>>();           // 32768 rows
    k4_mix   <<<256,  256>>>();           // 2048 modes / 8 per block
    kB_inv   <<<1536, 128, 98304>>>(out); // 256 bd * 6 w-groups
}

// round 7
// speedup vs baseline: 1.8224x; 1.1052x over previous
#include <cuda_runtime.h>

// Problem constants
#define BB 8
#define CC 32
#define DD 32
#define TT 32
#define HH 96
#define WW 96
#define MT 8
#define MS 16
#define BC (BB*CC)        // 256
#define BD (BB*DD)        // 256
#define HW (HH*WW)        // 9216
#define NMODE (MT*MS*MS)  // 2048
#define NROW (BC*MT*MS)   // 32768 rows of F2
#define TWO_PI 6.28318530717958647692f

// ---------------- scratch (static device globals; no allocation) ----------------
__device__ float g_F2r[WW*NROW];         // after T+H DFT, W-MAJOR: (w, bc*128+kt*16+kx)
__device__ float g_F2i[WW*NROW];
__device__ float g_F3r[BC*NMODE];        // after W-DFT: (bc, m)  m = kt*256+kx*16+ky
__device__ float g_F3i[BC*NMODE];
__device__ float g_Sr [BD*NMODE];        // after mix:   (bd, m)
__device__ float g_Si [BD*NMODE];

// ---------------- compile-time trig (Taylor, double precision) ----------------
__host__ __device__ constexpr double ct_cos(double x) {
    double x2 = x * x, t = 1.0, s = 1.0;
    for (int k = 1; k <= 26; k++) { t *= -x2 / ((2.0*k - 1.0) * (2.0*k)); s += t; }
    return s;
}
__host__ __device__ constexpr double ct_sin(double x) {
    double x2 = x * x, t = x, s = x;
    for (int k = 1; k <= 26; k++) { t *= -x2 / ((2.0*k) * (2.0*k + 1.0)); s += t; }
    return s;
}

// Twiddle cos/sin(2*pi*P/N) with exact 0 / +-1 at quadrant points
template<int P, int N> struct TW {
    static constexpr int    q0 = ((P % N) + N) % N;
    static constexpr int    aq = (q0 > N - q0) ? (N - q0) : q0;
    static constexpr int    ss = (q0 > N/2) ? -1 : 1;
    static constexpr bool c_zero = (4*aq == N);
    static constexpr bool s_zero = (aq == 0) || (2*aq == N);
    static constexpr float c =
        (aq == 0)     ? 1.0f  :
        (2*aq == N)   ? -1.0f :
        c_zero        ? 0.0f  :
        (float)ct_cos(6.283185307179586476925286766559 * (double)aq / (double)N);
    static constexpr float s =
        s_zero        ? 0.0f :
        (4*aq == N)   ? (ss > 0 ? 1.0f : -1.0f) :
        (float)(ss * ct_sin(6.283185307179586476925286766559 * (double)aq / (double)N));
};

template<int P, int N, int SG = 1>
__device__ __forceinline__ float fC(float v, float acc) {
    using T = TW<P, N>;
    constexpr float cc = (SG < 0) ? -T::c : T::c;
    if constexpr (T::c_zero)         return acc;
    else if constexpr (cc ==  1.0f)  return acc + v;
    else if constexpr (cc == -1.0f)  return acc - v;
    else                             return fmaf(v, cc, acc);
}
template<int P, int N, int SG = 1>
__device__ __forceinline__ float fS(float v, float acc) {
    using T = TW<P, N>;
    constexpr float sv = (SG < 0) ? -T::s : T::s;
    if constexpr (T::s_zero)         return acc;
    else if constexpr (sv ==  1.0f)  return acc + v;
    else if constexpr (sv == -1.0f)  return acc - v;
    else                             return fmaf(v, sv, acc);
}

// ---------------- compile-time unroller ----------------
template<int I> struct Ic { static constexpr int v = I; };
template<int I, int E, class F> __device__ __forceinline__ void UNR(F&& f) {
    if constexpr (I < E) { f(Ic<I>{}); UNR<I+1, E>(f); }
}

// ---------------- KA: fused T-DFT + H-DFT  (x -> F2, w-major), 256 thr ----------------
// smem Y layout: [h][kt][wl] -> h*128 + kt*16 + wl
__global__ void __launch_bounds__(256) kA_fwd(const float* __restrict__ x) {
    extern __shared__ float sm[];
    float* Yr = sm;                     // 12288 floats
    float* Yi = sm + 12288;
    const int tid = threadIdx.x;
    const int bc = blockIdx.x / 6;
    const int w0 = (blockIdx.x % 6) * 16;
    const float* xb = x + (size_t)bc * TT * HW + w0;

    const int wl = tid & 15;

    // phase1: T-DFT (real -> complex), folded over t <-> 32-t. 16 hs groups x 6 passes.
    {
        const int hs = tid >> 4;            // 0..15
        for (int p = 0; p < 6; p++) {
            const int h = p * 16 + hs;
            const float* xp = xb + h * WW + wl;
            float ar[MT], ai[MT];
            float x0  = xp[0];
            float x16 = xp[16 * HW];
            UNR<0,MT>([&](auto K){ constexpr int k = decltype(K)::v;
                ar[k] = (k & 1) ? (x0 - x16) : (x0 + x16);
                ai[k] = 0.0f; });
            UNR<1,16>([&](auto T){ constexpr int t = decltype(T)::v;
                float a = xp[(size_t)t * HW];
                float b = xp[(size_t)(TT - t) * HW];
                float pt = a + b, mt = a - b;
                UNR<0,MT>([&](auto K){ constexpr int k = decltype(K)::v;
                    ar[k] = fC<t*k, TT>(pt, ar[k]);
                    ai[k] = fS<t*k, TT, -1>(mt, ai[k]);
                });
            });
            UNR<0,MT>([&](auto K){ constexpr int k = decltype(K)::v;
                Yr[h*128 + k*16 + wl] = ar[k];
                Yi[h*128 + k*16 + wl] = ai[k]; });
        }
    }
    __syncthreads();

    // phase2: H-DFT (complex), folded over h <-> 96-h. kx split in two halves.
    {
        const int kt   = (tid >> 4) & 7;
        const int half = tid >> 7;
        const float* yr = Yr + kt*16 + wl;
        const float* yi = Yi + kt*16 + wl;
        auto run = [&](auto K0C){
            constexpr int K0 = decltype(K0C)::v;
            float fr[8], fi[8];
            float a0  = yr[0],      b0  = yi[0];
            float a48 = yr[48*128], b48 = yi[48*128];
            UNR<0,8>([&](auto J){ constexpr int j = decltype(J)::v; constexpr int kx = K0 + j;
                fr[j] = (kx & 1) ? (a0 - a48) : (a0 + a48);
                fi[j] = (kx & 1) ? (b0 - b48) : (b0 + b48); });
            UNR<1,48>([&](auto H){ constexpr int h = decltype(H)::v;
                float a  = yr[h*128],      b  = yi[h*128];
                float a2 = yr[(96-h)*128], b2 = yi[(96-h)*128];
                float pa = a + a2, ma = a - a2, pb = b + b2, mb = b - b2;
                UNR<0,8>([&](auto J){ constexpr int j = decltype(J)::v; constexpr int kx = K0 + j;
                    fr[j] = fC<h*kx, HH>(pa, fS<h*kx, HH>(mb, fr[j]));
                    fi[j] = fC<h*kx, HH>(pb, fS<h*kx, HH, -1>(ma, fi[j]));
                });
            });
            size_t base = (size_t)(w0 + wl) * NROW + bc*128 + kt*16 + K0;
            UNR<0,8>([&](auto J){ constexpr int j = decltype(J)::v;
                g_F2r[base + j] = fr[j];
                g_F2i[base + j] = fi[j]; });
        };
        if (half == 0) run(Ic<0>{}); else run(Ic<8>{});
    }
}

// ---------------- K3: W-DFT (F2 -> F3), coalesced, folded over w <-> 96-w ----------------
__global__ void __launch_bounds__(128) k3_wdft() {
    int r = blockIdx.x * 128 + threadIdx.x;       // 32768 rows, exact
    const float* pr = g_F2r + r;
    const float* pi = g_F2i + r;
    float fr[MS], fi[MS];
    {
        float a0  = pr[0],                  b0  = pi[0];
        float a48 = pr[(size_t)48 * NROW],  b48 = pi[(size_t)48 * NROW];
        UNR<0,MS>([&](auto K){ constexpr int ky = decltype(K)::v;
            fr[ky] = (ky & 1) ? (a0 - a48) : (a0 + a48);
            fi[ky] = (ky & 1) ? (b0 - b48) : (b0 + b48); });
    }
    UNR<1,48>([&](auto WI){ constexpr int w = decltype(WI)::v;
        float a  = pr[(size_t)w * NROW],      b  = pi[(size_t)w * NROW];
        float a2 = pr[(size_t)(96-w) * NROW], b2 = pi[(size_t)(96-w) * NROW];
        float pa = a + a2, ma = a - a2, pb = b + b2, mb = b - b2;
        UNR<0,MS>([&](auto K){ constexpr int ky = decltype(K)::v;
            fr[ky] = fC<w*ky, WW>(pa, fS<w*ky, WW>(mb, fr[ky]));
            fi[ky] = fC<w*ky, WW>(pb, fS<w*ky, WW, -1>(ma, fi[ky]));
        });
    });
    size_t o = (size_t)r * MS;
    UNR<0,MS>([&](auto K){ constexpr int ky = decltype(K)::v;
        g_F3r[o + ky] = fr[ky];
        g_F3i[o + ky] = fi[ky]; });
}

// ---------------- K4: channel mix, weights read in ORIGINAL layout ----------------
// block = 8 modes; thread = (d, ml); 8 batch accumulators. scale folded at writeout.
__global__ void __launch_bounds__(256) k4_mix(const float* __restrict__ wr,
                                              const float* __restrict__ wi) {
    __shared__ float Xr[BC*8], Xi[BC*8];         // 16 KB
    const int m0 = blockIdx.x * 8;
    const int tid = threadIdx.x;
    for (int i = tid; i < BC*8; i += 256) {
        int bcc = i >> 3, mm = i & 7;
        Xr[i] = g_F3r[(size_t)bcc * NMODE + m0 + mm];
        Xi[i] = g_F3i[(size_t)bcc * NMODE + m0 + mm];
    }
    __syncthreads();
    const int d  = tid >> 3;
    const int ml = tid & 7;
    const int m  = m0 + ml;

    float sr[BB], si[BB];
#pragma unroll
    for (int b = 0; b < BB; b++) { sr[b] = 0.0f; si[b] = 0.0f; }

#pragma unroll 4
    for (int c = 0; c < CC; c++) {
        float a  = wr[(size_t)(c*DD + d) * NMODE + m];
        float bb = wi[(size_t)(c*DD + d) * NMODE + m];
#pragma unroll
        for (int b = 0; b < BB; b++) {
            float xr = Xr[(b*CC + c)*8 + ml];
            float xi = Xi[(b*CC + c)*8 + ml];
            sr[b] = fmaf(xr, a,  fmaf(-xi, bb, sr[b]));
            si[b] = fmaf(xr, bb, fmaf( xi, a,  si[b]));
        }
    }
    float sc = (((m & (MS-1)) == 0) ? 1.0f : 2.0f) * (1.0f / 294912.0f);
#pragma unroll
    for (int b = 0; b < BB; b++) {
        size_t o = (size_t)(b*DD + d) * NMODE + m;
        g_Sr[o] = sr[b] * sc;
        g_Si[o] = si[b] * sc;
    }
}

// ---------------- KB: fused W-expand + H-expand + T-expand  (S -> out), 256 thr ----------------
// smem: Z [24576] + a1 [4096] = 28672 floats = 114688 B
__global__ void __launch_bounds__(256) kB_inv(float* __restrict__ out) {
    extern __shared__ float sm[];
    float* Zr = sm;                              // 12288 floats
    float* Zi = sm + 12288;
    float* a1r = sm + 24576;                     // [kt][kx][wl] 2048 floats
    float* a1i = sm + 24576 + 2048;
    float*  Ssr = sm;                            // phase0 staging aliases Z
    float*  Ssi = sm + 2048;
    float2* tab = reinterpret_cast<float2*>(sm + 4096);   // [ky][wl] 256 float2

    const int tid = threadIdx.x;
    const int bd = blockIdx.x / 6;
    const int w0 = (blockIdx.x % 6) * 16;
    const int wl = tid & 15;

    {   // load S tile (coalesced) + per-block w table
        const float* srp = g_Sr + (size_t)bd * NMODE;
        const float* sip = g_Si + (size_t)bd * NMODE;
        for (int i = tid; i < NMODE; i += 256) { Ssr[i] = srp[i]; Ssi[i] = sip[i]; }
        if (tid < 256) {
            int ky = tid >> 4, wl2 = tid & 15;
            float ssin, ccos;
            sincosf(TWO_PI * (float)((ky * (w0 + wl2)) % WW) / (float)WW, &ssin, &ccos);
            tab[tid] = make_float2(ccos, ssin);
        }
    }
    __syncthreads();

    const int kt   = (tid >> 4) & 7;
    const int half = tid >> 7;

    // phase0: W-expand, e^{+i 2pi ky w / 96}; each half does 8 kx -> smem a1
    {
        float ec[MS], es[MS];
#pragma unroll
        for (int ky = 0; ky < MS; ky++) { float2 e = tab[ky*16 + wl]; ec[ky] = e.x; es[ky] = e.y; }
#pragma unroll
        for (int j = 0; j < 8; j++) {
            int kx = half*8 + j;
            const float* pr = Ssr + (kt*MS + kx) * MS;
            const float* pi = Ssi + (kt*MS + kx) * MS;
            float rr = 0.f, ii = 0.f;
#pragma unroll
            for (int ky = 0; ky < MS; ky++) {
                float sv = pr[ky], iv = pi[ky];
                rr = fmaf(sv, ec[ky], fmaf(-iv, es[ky], rr));
                ii = fmaf(sv, es[ky], fmaf( iv, ec[ky], ii));
            }
            a1r[kt*256 + kx*16 + wl] = rr;
            a1i[kt*256 + kx*16 + wl] = ii;
        }
    }
    __syncthreads();   // a1 complete; Ss/tab reads done before Z overwrites

    // phase1: H-expand, folded over output h <-> 96-h; halves split the h range
    {
        float xr[MS], xi[MS];
#pragma unroll
        for (int kx = 0; kx < MS; kx++) {
            xr[kx] = a1r[kt*256 + kx*16 + wl];
            xi[kx] = a1i[kt*256 + kx*16 + wl];
        }
        auto body = [&](auto H){ constexpr int h = decltype(H)::v;
            float C = 0.f, S = 0.f, C2 = 0.f, S2 = 0.f;
            UNR<0,MS>([&](auto KX){ constexpr int kx = decltype(KX)::v;
                C  = fC<kx*h, HH>(xr[kx], C);
                C2 = fC<kx*h, HH>(xi[kx], C2);
                S  = fS<kx*h, HH>(xi[kx], S);
                S2 = fS<kx*h, HH>(xr[kx], S2);
            });
            Zr[h*128 + kt*16 + wl] = C - S;
            Zi[h*128 + kt*16 + wl] = C2 + S2;
            if constexpr (h >= 1 && h <= 47) {
                Zr[(96-h)*128 + kt*16 + wl] = C + S;
                Zi[(96-h)*128 + kt*16 + wl] = C2 - S2;
            }
        };
        if (half == 0) UNR<0,25>(body); else UNR<25,49>(body);
    }
    __syncthreads();

    // phase2: T-expand + real part, folded over output t <-> 32-t. 16 hs x 6 passes.
    float* ob = out + (size_t)bd * TT * HW + w0;
    const int hs = tid >> 4;            // 0..15
    for (int p = 0; p < 6; p++) {
        const int h = p * 16 + hs;
        float zr[MT], zi[MT];
        UNR<0,MT>([&](auto K){ constexpr int k = decltype(K)::v;
            zr[k] = Zr[h*128 + k*16 + wl];
            zi[k] = Zi[h*128 + k*16 + wl]; });
        float* op = ob + h * WW + wl;
        {   // t = 0 and t = 16
            float s0 = 0.f, s16 = 0.f;
            UNR<0,MT>([&](auto K){ constexpr int k = decltype(K)::v;
                s0 += zr[k];
                s16 = (k & 1) ? (s16 - zr[k]) : (s16 + zr[k]); });
            op[0] = s0;
            op[(size_t)16 * HW] = s16;
        }
        UNR<1,16>([&](auto T){ constexpr int t = decltype(T)::v;
            float C = 0.f, S = 0.f;
            UNR<0,MT>([&](auto K){ constexpr int k = decltype(K)::v;
                C = fC<k*t, TT>(zr[k], C);
                S = fS<k*t, TT>(zi[k], S);
            });
            op[(size_t)t * HW]        = C - S;
            op[(size_t)(32 - t) * HW] = C + S;
        });
    }
}

// ---------------- launch ----------------
extern "C" void kernel_launch(void* const* d_in, const int* in_sizes, int n_in,
                              void* d_out, int out_size) {
    (void)in_sizes; (void)n_in; (void)out_size;
    const float* x  = (const float*)d_in[0];
    const float* wr = (const float*)d_in[1];
    const float* wi = (const float*)d_in[2];
    float* out = (float*)d_out;

    cudaFuncSetAttribute(kA_fwd, cudaFuncAttributeMaxDynamicSharedMemorySize, 98304);
    cudaFuncSetAttribute(kB_inv, cudaFuncAttributeMaxDynamicSharedMemorySize, 114688);

    kA_fwd <<<1536, 256, 98304>>>(x);    // 256 bc * 6 w-groups
    k3_wdft<<<256,  128>>>();            // 32768 rows
    k4_mix <<<256,  256>>>(wr, wi);      // 2048 modes / 8 per block
    kB_inv <<<1536, 256, 114688>>>(out); // 256 bd * 6 w-groups
}